// round 1
// baseline (speedup 1.0000x reference)
#include <cuda_runtime.h>
#include <stdint.h>

// ---------------------------------------------------------------------------
// ClipperEventEncoder: LIF spiking recurrence (tau=2, v_th=1, hard reset)
// followed by conv3x3(1->4)+relu, conv3x3(4->1)+relu, mean over T.
//
// Key structure: the spike map s_t is a pure per-pixel function of the time
// recurrence (no spatial coupling), and the convs only see s_t. So:
//   kernel 1: elementwise LIF over time, emit spike BITMASKS (1 bit/px/step)
//             -> 3.1 MB scratch, L2 resident. This is the only pass that
//             touches the 100.7 MB input: memory-bound by construction.
//   kernel 2: per output tile, per time step, check the tile+halo bitmask;
//             if no spikes, y_t == relu(conv(relu(conv(0)))) == 0 (no bias),
//             so the step contributes nothing. Only spiking steps pay for
//             the conv pipeline (shared-memory tile conv, correct for any
//             input). With x ~ U[0,1), v=(v+x)/2 stays < 1 forever, so for
//             this problem instance every step is skipped and total runtime
//             is ~ (one streaming pass over x) + (output write).
// ---------------------------------------------------------------------------

#define IMG_H 512
#define IMG_W 512
#define HW (IMG_H * IMG_W)
#define T_STEPS 96
#define WPR (IMG_W / 32)               // 16 bitmask words per image row
#define WORDS_PER_T (IMG_H * WPR)      // 8192
#define MASK_WORDS (T_STEPS * WORDS_PER_T)

// 3 MB spike bitmask scratch (static device allocation: allowed).
__device__ uint32_t g_spike_mask[MASK_WORDS];

// ---------------------------------------------------------------------------
// Kernel 1: LIF recurrence -> spike bitmasks.
// One thread per pixel; grid covers all 262144 pixels exactly.
// Loads are streaming (read-once), v lives in a register, the only output
// is one ballot word per warp per step.
// ---------------------------------------------------------------------------
__global__ void __launch_bounds__(256, 8)
lif_spike_kernel(const float* __restrict__ x)
{
    const int px    = blockIdx.x * 256 + threadIdx.x;   // < HW by construction
    const int word  = px >> 5;
    const bool lane0 = ((threadIdx.x & 31) == 0);

    float v = 0.0f;

    #pragma unroll 4
    for (int t = 0; t < T_STEPS; ++t) {
        const float xt = __ldcs(&x[(size_t)t * HW + px]);   // streaming, read-once
        v = v + (xt - v) * 0.5f;                            // v + (x - v)/tau, tau=2
        const bool spike = (v >= 1.0f);                     // atan_spike(v - 1) forward
        const uint32_t m = __ballot_sync(0xffffffffu, spike);
        if (spike) v = 0.0f;                                // hard reset
        if (lane0) g_spike_mask[t * WORDS_PER_T + word] = m;
    }
}

// ---------------------------------------------------------------------------
// Kernel 2: per-tile conv pipeline with per-timestep spike skip.
// Tile: 32x32 outputs, 256 threads (4 outputs/thread).
// Shared: spike region 36x36 (2-halo), h region 34x34 x 4ch (1-halo).
// ---------------------------------------------------------------------------
#define TILE 32
#define SREG 36          // spike region edge  (TILE + 4)
#define HREG 34          // h region edge      (TILE + 2)

__global__ void __launch_bounds__(256, 4)
conv_accum_kernel(const float* __restrict__ w1,   // [4,1,3,3]
                  const float* __restrict__ w2,   // [1,4,3,3]
                  float* __restrict__ out)        // [512,512]
{
    __shared__ uint32_t sflag[T_STEPS];
    __shared__ float    ssp[SREG][SREG + 4];        // spikes (+4 pad: bank stagger)
    __shared__ float    sh[4][HREG][HREG + 2];      // relu(conv1) per channel
    __shared__ float    sw1[36];
    __shared__ float    sw2[36];

    const int tid = threadIdx.x;
    const int x0  = blockIdx.x * TILE;
    const int y0  = blockIdx.y * TILE;
    const int wx0 = x0 >> 5;

    for (int i = tid; i < T_STEPS; i += 256) sflag[i] = 0u;
    if (tid < 36) { sw1[tid] = w1[tid]; sw2[tid] = w2[tid]; }
    __syncthreads();

    // ---- Phase A: per-timestep "any spike near this tile" flags ----------
    // Words covering columns [x0-32, x0+63] x rows [y0-2, y0+33]: superset of
    // the true 2-pixel halo -> may occasionally run a conv step it didn't
    // need (still correct), never skips a needed one.
    for (int idx = tid; idx < T_STEPS * SREG * 3; idx += 256) {
        const int t   = idx / (SREG * 3);
        const int r   = idx % (SREG * 3);
        const int yy  = r / 3;
        const int wxo = (r % 3) - 1;
        const int gy  = y0 - 2 + yy;
        const int wx  = wx0 + wxo;
        if (gy < 0 || gy >= IMG_H || wx < 0 || wx >= WPR) continue;
        const uint32_t m = g_spike_mask[t * WORDS_PER_T + gy * WPR + wx];
        if (m) atomicOr(&sflag[t], m);
    }
    __syncthreads();

    float acc[4] = {0.0f, 0.0f, 0.0f, 0.0f};

    for (int t = 0; t < T_STEPS; ++t) {
        if (sflag[t] == 0u) continue;          // uniform branch: flag is shared

        // ---- decode spike bits -> float tile (zero padded at image edge) --
        for (int i = tid; i < SREG * SREG; i += 256) {
            const int yy = i / SREG, xx = i % SREG;
            const int gy = y0 - 2 + yy, gx = x0 - 2 + xx;
            float s = 0.0f;
            if (gy >= 0 && gy < IMG_H && gx >= 0 && gx < IMG_W) {
                const uint32_t m = g_spike_mask[t * WORDS_PER_T + gy * WPR + (gx >> 5)];
                s = ((m >> (gx & 31)) & 1u) ? 1.0f : 0.0f;
            }
            ssp[yy][xx] = s;
        }
        __syncthreads();   // also orders previous iteration's sh reads vs writes below

        // ---- conv1 (1->4) + relu over the 34x34 h region -----------------
        for (int i = tid; i < HREG * HREG; i += 256) {
            const int hy = i / HREG, hx = i % HREG;
            float a0 = 0.f, a1 = 0.f, a2 = 0.f, a3 = 0.f;
            #pragma unroll
            for (int ky = 0; ky < 3; ++ky) {
                #pragma unroll
                for (int kx = 0; kx < 3; ++kx) {
                    const float s = ssp[hy + ky][hx + kx];
                    const int  k = ky * 3 + kx;
                    a0 += sw1[ 0 + k] * s;
                    a1 += sw1[ 9 + k] * s;
                    a2 += sw1[18 + k] * s;
                    a3 += sw1[27 + k] * s;
                }
            }
            sh[0][hy][hx] = fmaxf(a0, 0.f);
            sh[1][hy][hx] = fmaxf(a1, 0.f);
            sh[2][hy][hx] = fmaxf(a2, 0.f);
            sh[3][hy][hx] = fmaxf(a3, 0.f);
        }
        __syncthreads();

        // ---- conv2 (4->1) + relu, accumulate into per-thread outputs -----
        #pragma unroll
        for (int k = 0; k < 4; ++k) {
            const int o  = tid + 256 * k;
            const int oy = o >> 5;
            const int ox = o & 31;
            float a = 0.0f;
            #pragma unroll
            for (int c = 0; c < 4; ++c) {
                #pragma unroll
                for (int ky = 0; ky < 3; ++ky) {
                    #pragma unroll
                    for (int kx = 0; kx < 3; ++kx) {
                        a += sw2[c * 9 + ky * 3 + kx] * sh[c][oy + ky][ox + kx];
                    }
                }
            }
            acc[k] += fmaxf(a, 0.0f);
        }
        // No barrier needed here: next iteration's first write (ssp) does not
        // alias sh, and the decode barrier orders sh reuse.
    }

    // ---- mean over T and store -------------------------------------------
    const float inv_t = 1.0f / (float)T_STEPS;
    #pragma unroll
    for (int k = 0; k < 4; ++k) {
        const int o  = tid + 256 * k;
        const int oy = o >> 5;
        const int ox = o & 31;
        out[(size_t)(y0 + oy) * IMG_W + (x0 + ox)] = acc[k] * inv_t;
    }
}

// ---------------------------------------------------------------------------
extern "C" void kernel_launch(void* const* d_in, const int* in_sizes, int n_in,
                              void* d_out, int out_size)
{
    const float* x_seq = (const float*)d_in[0];   // [96, 512, 512] fp32
    const float* w1    = (const float*)d_in[1];   // [4,1,3,3] fp32
    const float* w2    = (const float*)d_in[2];   // [1,4,3,3] fp32
    float*       out   = (float*)d_out;           // [512,512] fp32

    lif_spike_kernel<<<HW / 256, 256>>>(x_seq);
    conv_accum_kernel<<<dim3(IMG_W / TILE, IMG_H / TILE), 256>>>(w1, w2, out);
}

// round 4
// speedup vs baseline: 1.4355x; 1.4355x over previous
#include <cuda_runtime.h>
#include <stdint.h>

// ---------------------------------------------------------------------------
// ClipperEventEncoder: LIF recurrence (tau=2, v_th=1, hard reset) ->
// conv3x3(1->4)+relu -> conv3x3(4->1)+relu -> mean over T.
//
//  k1: elementwise LIF over T. NO ballots inside the memory loop (warp
//      convergence points kill load MLP). Each thread packs its 96 spike
//      bits into 3 registers. After the loop:
//        - warp-OR (__reduce_or_sync) of the 3 bit-registers gives a per-
//          mask-word 96-bit "any spike at step t" summary -> g_word_any
//          (3 words/mask-word, stored unconditionally: no races, no
//          pre-zero pass).
//        - zero-spike warps (the common case for this input) fill their 96
//          mask words with zeros, lane-coalesced ([word][t] layout).
//        - spiking warps ballot-transpose bits -> per-t mask words.
//      One streaming pass over the 100.7 MB input: memory-floor bound.
//  k2: per 32x32 tile, OR the 108x3 halo summary words -> 3 skip bitmasks;
//      run the shared-memory conv pipeline only for timesteps with spikes
//      near the tile; mean over T; store. With x ~ U[0,1) the membrane
//      potential v=(v+x)/2 stays < 1 forever (exact in fp32: near the
//      threshold x-v is Sterbenz-exact and the sum <= 1-2^-24 never rounds
//      to 1.0), so zero spikes -> k2 is just the 1 MB output write. The
//      conv path remains fully correct for arbitrary inputs.
// ---------------------------------------------------------------------------

#define IMG_H 512
#define IMG_W 512
#define HW (IMG_H * IMG_W)
#define T_STEPS 96
#define WPR (IMG_W / 32)                 // 16 mask words per image row
#define NWORDS (IMG_H * WPR)             // 8192 words per time step

// Mask layout: [word][t]  (word-major so per-warp zero fill is coalesced)
__device__ uint32_t g_spike_mask[NWORDS * T_STEPS];   // 3.1 MB
// Per-word timestep summary: [word][chunk], chunk = t/32. bit (t%32) set
// iff any of the word's 32 pixels spiked at step t.
__device__ uint32_t g_word_any[NWORDS * 3];           // 96 KB

// ---------------------------------------------------------------------------
// Kernel 1: LIF recurrence. 1 thread per pixel, 1024 blocks x 256.
// ---------------------------------------------------------------------------
__global__ void __launch_bounds__(256, 8)
lif_spike_kernel(const float* __restrict__ x)
{
    const int px   = blockIdx.x * 256 + threadIdx.x;
    const int lane = threadIdx.x & 31;
    const int word = px >> 5;                          // global mask-word index

    float v = 0.0f;
    uint32_t bits0 = 0u, bits1 = 0u, bits2 = 0u;

    const float* __restrict__ p = x + px;

    // Pure load/ALU loop: no syncs -> loads hoistable -> MLP = unroll depth.
    #pragma unroll 8
    for (int t = 0; t < T_STEPS; ++t) {
        const float xt = __ldcs(p);                    // streaming, read-once
        p += HW;
        v = v + (xt - v) * 0.5f;                       // v + (x - v)/tau, tau=2
        const uint32_t s = (v >= 1.0f) ? 1u : 0u;
        if (t < 32)       bits0 |= s << t;
        else if (t < 64)  bits1 |= s << (t - 32);
        else              bits2 |= s << (t - 64);
        if (s) v = 0.0f;                               // hard reset
    }

    // Warp-wide per-timestep "any spike in this word" summaries.
    const uint32_t any0 = __reduce_or_sync(0xffffffffu, bits0);
    const uint32_t any1 = __reduce_or_sync(0xffffffffu, bits1);
    const uint32_t any2 = __reduce_or_sync(0xffffffffu, bits2);

    if (lane == 0) {
        g_word_any[word * 3 + 0] = any0;
        g_word_any[word * 3 + 1] = any1;
        g_word_any[word * 3 + 2] = any2;
    }

    uint32_t* wbase = &g_spike_mask[(size_t)word * T_STEPS];

    if ((any0 | any1 | any2) == 0u) {
        // Common case: no spikes in this warp's 32 pixels across all T.
        // Fill the warp's word-column with zeros, lane-coalesced, streaming.
        __stcs(&wbase[lane],      0u);
        __stcs(&wbase[lane + 32], 0u);
        __stcs(&wbase[lane + 64], 0u);
        return;
    }

    // Rare case: transpose per-thread bits -> per-t mask words. The ballot
    // guard condition (anyX bit) is warp-uniform, so no divergence hazard.
    #pragma unroll 1
    for (int t = 0; t < T_STEPS; ++t) {
        uint32_t anyb, b;
        if (t < 32)      { anyb = (any0 >> t) & 1u;        b = (bits0 >> t) & 1u; }
        else if (t < 64) { anyb = (any1 >> (t - 32)) & 1u; b = (bits1 >> (t - 32)) & 1u; }
        else             { anyb = (any2 >> (t - 64)) & 1u; b = (bits2 >> (t - 64)) & 1u; }
        uint32_t m = 0u;
        if (anyb) m = __ballot_sync(0xffffffffu, b != 0u);
        if (lane == 0) wbase[t] = m;
    }
}

// ---------------------------------------------------------------------------
// Kernel 2: per-tile conv pipeline with per-timestep spike skip.
// Tile: 32x32 outputs, 256 threads (4 outputs/thread).
// ---------------------------------------------------------------------------
#define TILE 32
#define SREG 36          // spike region edge (TILE + 4)
#define HREG 34          // h region edge     (TILE + 2)

__global__ void __launch_bounds__(256, 4)
conv_accum_kernel(const float* __restrict__ w1,   // [4,1,3,3]
                  const float* __restrict__ w2,   // [1,4,3,3]
                  float* __restrict__ out)        // [512,512]
{
    __shared__ uint32_t sany[3];
    __shared__ float    ssp[SREG][SREG + 4];
    __shared__ float    sh[4][HREG][HREG + 2];
    __shared__ float    sw1[36];
    __shared__ float    sw2[36];

    const int tid = threadIdx.x;
    const int x0  = blockIdx.x * TILE;
    const int y0  = blockIdx.y * TILE;
    const int wx0 = x0 >> 5;

    if (tid < 36) { sw1[tid] = w1[tid]; sw2[tid] = w2[tid]; }
    if (tid < 3)  sany[tid] = 0u;
    __syncthreads();

    // ---- Phase A: OR the halo region's per-word timestep summaries -------
    // Words covering columns [x0-32, x0+63] x rows [y0-2, y0+33]: superset
    // of the true 2-px halo (may run an unneeded step; never skips a needed
    // one). 108 (row, wordcol) pairs x 3 chunks.
    {
        uint32_t l0 = 0u, l1 = 0u, l2 = 0u;
        for (int i = tid; i < 36 * 3; i += 256) {
            const int r   = i / 3;
            const int wxo = i % 3 - 1;
            const int gy  = y0 - 2 + r;
            const int wx  = wx0 + wxo;
            if (gy >= 0 && gy < IMG_H && wx >= 0 && wx < WPR) {
                const uint32_t* a = &g_word_any[(gy * WPR + wx) * 3];
                l0 |= a[0]; l1 |= a[1]; l2 |= a[2];
            }
        }
        if (l0) atomicOr(&sany[0], l0);
        if (l1) atomicOr(&sany[1], l1);
        if (l2) atomicOr(&sany[2], l2);
    }
    __syncthreads();

    const uint32_t a0 = sany[0], a1 = sany[1], a2 = sany[2];

    float acc[4] = {0.0f, 0.0f, 0.0f, 0.0f};

    if (a0 | a1 | a2) {
        for (int t = 0; t < T_STEPS; ++t) {
            const uint32_t chunk = (t < 32) ? a0 : (t < 64) ? a1 : a2;
            if (!((chunk >> (t & 31)) & 1u)) continue;   // uniform branch

            // ---- decode spike bits -> float tile (zero-padded at edges) ---
            for (int i = tid; i < SREG * SREG; i += 256) {
                const int yy = i / SREG, xx = i % SREG;
                const int gy = y0 - 2 + yy, gx = x0 - 2 + xx;
                float s = 0.0f;
                if (gy >= 0 && gy < IMG_H && gx >= 0 && gx < IMG_W) {
                    const int w = gy * WPR + (gx >> 5);
                    const uint32_t m = g_spike_mask[(size_t)w * T_STEPS + t];
                    s = ((m >> (gx & 31)) & 1u) ? 1.0f : 0.0f;
                }
                ssp[yy][xx] = s;
            }
            __syncthreads();   // also orders prior iter's sh reads vs writes

            // ---- conv1 (1->4) + relu over the 34x34 h region --------------
            for (int i = tid; i < HREG * HREG; i += 256) {
                const int hy = i / HREG, hx = i % HREG;
                float b0 = 0.f, b1 = 0.f, b2 = 0.f, b3 = 0.f;
                #pragma unroll
                for (int ky = 0; ky < 3; ++ky) {
                    #pragma unroll
                    for (int kx = 0; kx < 3; ++kx) {
                        const float s = ssp[hy + ky][hx + kx];
                        const int  k = ky * 3 + kx;
                        b0 += sw1[ 0 + k] * s;
                        b1 += sw1[ 9 + k] * s;
                        b2 += sw1[18 + k] * s;
                        b3 += sw1[27 + k] * s;
                    }
                }
                sh[0][hy][hx] = fmaxf(b0, 0.f);
                sh[1][hy][hx] = fmaxf(b1, 0.f);
                sh[2][hy][hx] = fmaxf(b2, 0.f);
                sh[3][hy][hx] = fmaxf(b3, 0.f);
            }
            __syncthreads();

            // ---- conv2 (4->1) + relu, accumulate --------------------------
            #pragma unroll
            for (int k = 0; k < 4; ++k) {
                const int o  = tid + 256 * k;
                const int oy = o >> 5;
                const int ox = o & 31;
                float a = 0.0f;
                #pragma unroll
                for (int c = 0; c < 4; ++c) {
                    #pragma unroll
                    for (int ky = 0; ky < 3; ++ky) {
                        #pragma unroll
                        for (int kx = 0; kx < 3; ++kx) {
                            a += sw2[c * 9 + ky * 3 + kx] * sh[c][oy + ky][ox + kx];
                        }
                    }
                }
                acc[k] += fmaxf(a, 0.0f);
            }
            // No barrier needed: next decode writes ssp (disjoint from sh)
            // and its __syncthreads orders sh reuse.
        }
    }

    // ---- mean over T and store -------------------------------------------
    const float inv_t = 1.0f / (float)T_STEPS;
    #pragma unroll
    for (int k = 0; k < 4; ++k) {
        const int o  = tid + 256 * k;
        const int oy = o >> 5;
        const int ox = o & 31;
        out[(size_t)(y0 + oy) * IMG_W + (x0 + ox)] = acc[k] * inv_t;
    }
}

// ---------------------------------------------------------------------------
extern "C" void kernel_launch(void* const* d_in, const int* in_sizes, int n_in,
                              void* d_out, int out_size)
{
    const float* x_seq = (const float*)d_in[0];   // [96, 512, 512] fp32
    const float* w1    = (const float*)d_in[1];   // [4,1,3,3] fp32
    const float* w2    = (const float*)d_in[2];   // [1,4,3,3] fp32
    float*       out   = (float*)d_out;           // [512,512] fp32

    lif_spike_kernel<<<HW / 256, 256>>>(x_seq);                        // streaming pass
    conv_accum_kernel<<<dim3(IMG_W / TILE, IMG_H / TILE), 256>>>(w1, w2, out);
}

// round 5
// speedup vs baseline: 3.2964x; 2.2964x over previous
#include <cuda_runtime.h>
#include <stdint.h>

// ---------------------------------------------------------------------------
// ClipperEventEncoder: LIF recurrence (tau=2, v_th=1, hard reset) ->
// conv3x3(1->4)+relu -> conv3x3(4->1)+relu -> mean over T.
//
// R5 change (from ncu evidence): k1 was latency-bound at 2.4 TB/s because
// __launch_bounds__(256,8) capped regs at 32 -> MLP ~ 1. Now: 2 px/thread
// (lane-aligned, +32 apart -> warp owns exactly 2 mask words), explicit
// 16-load register batches (8 timesteps x 2 px) per iteration, full unroll
// so bit-chunk indices are compile-time. ~56 KB of loads in flight per SM
// vs ~25 KB needed for 7 TB/s.
//
// k2 unchanged: per-tile timestep skip via per-word 96-bit spike summaries;
// zero-spike input (x ~ U[0,1) keeps v < 1 forever, exactly in fp32) means
// it degenerates to the 1 MB output write. Conv path fully correct for any
// input.
// ---------------------------------------------------------------------------

#define IMG_H 512
#define IMG_W 512
#define HW (IMG_H * IMG_W)
#define T_STEPS 96
#define WPR (IMG_W / 32)                 // 16 mask words per image row
#define NWORDS (IMG_H * WPR)             // 8192 words per time step

// Mask layout: [word][t]  (word-major so per-warp zero fill is coalesced)
__device__ uint32_t g_spike_mask[NWORDS * T_STEPS];   // 3.1 MB
// Per-word timestep summary: [word][chunk], chunk = t/32. bit (t%32) set
// iff any of the word's 32 pixels spiked at step t.
__device__ uint32_t g_word_any[NWORDS * 3];           // 96 KB

// ---------------------------------------------------------------------------
// Kernel 1: LIF recurrence. 2 pixels/thread: pxA = seg+lane, pxB = seg+32+lane
// so each warp owns mask words 2*gw and 2*gw+1 with lane<->bit identity.
// 1024 blocks x 128 threads = 4096 warps x 64 px.
// ---------------------------------------------------------------------------
__global__ void __launch_bounds__(128)
lif_spike_kernel(const float* __restrict__ x)
{
    const int lane  = threadIdx.x & 31;
    const int gw    = blockIdx.x * 4 + (threadIdx.x >> 5);   // global warp id
    const int seg   = gw * 64;                               // first pixel of warp
    const int pxA   = seg + lane;
    const int pxB   = pxA + 32;
    const int wordA = gw * 2;
    const int wordB = wordA + 1;

    float vA = 0.0f, vB = 0.0f;
    uint32_t bitsA[3], bitsB[3];

    // Fully unrolled: c and tb+j are compile-time -> immediate shifts, no
    // local-memory spills, and ptxas can front-batch each 16-load group.
    #pragma unroll
    for (int c = 0; c < 3; ++c) {
        uint32_t aA = 0u, aB = 0u;
        #pragma unroll
        for (int tb = 0; tb < 32; tb += 8) {
            const float* __restrict__ base = x + (size_t)(c * 32 + tb) * HW;
            float ra[8], rb[8];
            #pragma unroll
            for (int j = 0; j < 8; ++j) {
                ra[j] = __ldcs(base + (size_t)j * HW + pxA);
                rb[j] = __ldcs(base + (size_t)j * HW + pxB);
            }
            #pragma unroll
            for (int j = 0; j < 8; ++j) {
                vA = vA + (ra[j] - vA) * 0.5f;               // v + (x-v)/tau
                const uint32_t sA = (vA >= 1.0f) ? 1u : 0u;
                aA |= sA << (tb + j);
                if (sA) vA = 0.0f;                            // hard reset

                vB = vB + (rb[j] - vB) * 0.5f;
                const uint32_t sB = (vB >= 1.0f) ? 1u : 0u;
                aB |= sB << (tb + j);
                if (sB) vB = 0.0f;
            }
        }
        bitsA[c] = aA;
        bitsB[c] = aB;
    }

    // Warp-wide per-timestep "any spike in this word" summaries (exact:
    // lane l of this warp IS bit l of word A / word B).
    uint32_t anyA[3], anyB[3];
    #pragma unroll
    for (int c = 0; c < 3; ++c) {
        anyA[c] = __reduce_or_sync(0xffffffffu, bitsA[c]);
        anyB[c] = __reduce_or_sync(0xffffffffu, bitsB[c]);
    }
    if (lane == 0) {
        #pragma unroll
        for (int c = 0; c < 3; ++c) {
            g_word_any[wordA * 3 + c] = anyA[c];
            g_word_any[wordB * 3 + c] = anyB[c];
        }
    }

    uint32_t* wA = &g_spike_mask[(size_t)wordA * T_STEPS];
    uint32_t* wB = &g_spike_mask[(size_t)wordB * T_STEPS];

    const uint32_t spA = anyA[0] | anyA[1] | anyA[2];   // warp-uniform
    const uint32_t spB = anyB[0] | anyB[1] | anyB[2];

    // Common case: zero-fill the warp's two word-columns, lane-coalesced.
    if (spA == 0u) {
        __stcs(&wA[lane], 0u); __stcs(&wA[lane + 32], 0u); __stcs(&wA[lane + 64], 0u);
    }
    if (spB == 0u) {
        __stcs(&wB[lane], 0u); __stcs(&wB[lane + 32], 0u); __stcs(&wB[lane + 64], 0u);
    }
    if ((spA | spB) == 0u) return;

    // Rare case: exact ballot transpose for whichever word spiked.
    if (spA != 0u) {
        #pragma unroll 1
        for (int t = 0; t < T_STEPS; ++t) {
            const int c = t >> 5, s = t & 31;
            uint32_t m = 0u;
            if ((anyA[c] >> s) & 1u)                          // warp-uniform guard
                m = __ballot_sync(0xffffffffu, (bitsA[c] >> s) & 1u);
            if (lane == 0) wA[t] = m;
        }
    }
    if (spB != 0u) {
        #pragma unroll 1
        for (int t = 0; t < T_STEPS; ++t) {
            const int c = t >> 5, s = t & 31;
            uint32_t m = 0u;
            if ((anyB[c] >> s) & 1u)
                m = __ballot_sync(0xffffffffu, (bitsB[c] >> s) & 1u);
            if (lane == 0) wB[t] = m;
        }
    }
}

// ---------------------------------------------------------------------------
// Kernel 2: per-tile conv pipeline with per-timestep spike skip.
// Tile: 32x32 outputs, 256 threads (4 outputs/thread).
// ---------------------------------------------------------------------------
#define TILE 32
#define SREG 36          // spike region edge (TILE + 4)
#define HREG 34          // h region edge     (TILE + 2)

__global__ void __launch_bounds__(256, 4)
conv_accum_kernel(const float* __restrict__ w1,   // [4,1,3,3]
                  const float* __restrict__ w2,   // [1,4,3,3]
                  float* __restrict__ out)        // [512,512]
{
    __shared__ uint32_t sany[3];
    __shared__ float    ssp[SREG][SREG + 4];
    __shared__ float    sh[4][HREG][HREG + 2];
    __shared__ float    sw1[36];
    __shared__ float    sw2[36];

    const int tid = threadIdx.x;
    const int x0  = blockIdx.x * TILE;
    const int y0  = blockIdx.y * TILE;
    const int wx0 = x0 >> 5;

    if (tid < 3) sany[tid] = 0u;
    __syncthreads();

    // ---- Phase A: OR the halo region's per-word timestep summaries -------
    // Words covering columns [x0-32, x0+63] x rows [y0-2, y0+33]: superset
    // of the true 2-px halo (may run an unneeded step; never skips a needed
    // one).
    {
        uint32_t l0 = 0u, l1 = 0u, l2 = 0u;
        for (int i = tid; i < 36 * 3; i += 256) {
            const int r   = i / 3;
            const int wxo = i % 3 - 1;
            const int gy  = y0 - 2 + r;
            const int wx  = wx0 + wxo;
            if (gy >= 0 && gy < IMG_H && wx >= 0 && wx < WPR) {
                const uint32_t* a = &g_word_any[(gy * WPR + wx) * 3];
                l0 |= a[0]; l1 |= a[1]; l2 |= a[2];
            }
        }
        if (l0) atomicOr(&sany[0], l0);
        if (l1) atomicOr(&sany[1], l1);
        if (l2) atomicOr(&sany[2], l2);
    }
    __syncthreads();

    const uint32_t a0 = sany[0], a1 = sany[1], a2 = sany[2];

    float acc[4] = {0.0f, 0.0f, 0.0f, 0.0f};

    if (a0 | a1 | a2) {
        if (tid < 36) { sw1[tid] = w1[tid]; sw2[tid] = w2[tid]; }
        __syncthreads();

        for (int t = 0; t < T_STEPS; ++t) {
            const uint32_t chunk = (t < 32) ? a0 : (t < 64) ? a1 : a2;
            if (!((chunk >> (t & 31)) & 1u)) continue;   // uniform branch

            // ---- decode spike bits -> float tile (zero-padded at edges) ---
            for (int i = tid; i < SREG * SREG; i += 256) {
                const int yy = i / SREG, xx = i % SREG;
                const int gy = y0 - 2 + yy, gx = x0 - 2 + xx;
                float s = 0.0f;
                if (gy >= 0 && gy < IMG_H && gx >= 0 && gx < IMG_W) {
                    const int w = gy * WPR + (gx >> 5);
                    const uint32_t m = g_spike_mask[(size_t)w * T_STEPS + t];
                    s = ((m >> (gx & 31)) & 1u) ? 1.0f : 0.0f;
                }
                ssp[yy][xx] = s;
            }
            __syncthreads();   // also orders prior iter's sh reads vs writes

            // ---- conv1 (1->4) + relu over the 34x34 h region --------------
            for (int i = tid; i < HREG * HREG; i += 256) {
                const int hy = i / HREG, hx = i % HREG;
                float b0 = 0.f, b1 = 0.f, b2 = 0.f, b3 = 0.f;
                #pragma unroll
                for (int ky = 0; ky < 3; ++ky) {
                    #pragma unroll
                    for (int kx = 0; kx < 3; ++kx) {
                        const float s = ssp[hy + ky][hx + kx];
                        const int  k = ky * 3 + kx;
                        b0 += sw1[ 0 + k] * s;
                        b1 += sw1[ 9 + k] * s;
                        b2 += sw1[18 + k] * s;
                        b3 += sw1[27 + k] * s;
                    }
                }
                sh[0][hy][hx] = fmaxf(b0, 0.f);
                sh[1][hy][hx] = fmaxf(b1, 0.f);
                sh[2][hy][hx] = fmaxf(b2, 0.f);
                sh[3][hy][hx] = fmaxf(b3, 0.f);
            }
            __syncthreads();

            // ---- conv2 (4->1) + relu, accumulate --------------------------
            #pragma unroll
            for (int k = 0; k < 4; ++k) {
                const int o  = tid + 256 * k;
                const int oy = o >> 5;
                const int ox = o & 31;
                float a = 0.0f;
                #pragma unroll
                for (int c = 0; c < 4; ++c) {
                    #pragma unroll
                    for (int ky = 0; ky < 3; ++ky) {
                        #pragma unroll
                        for (int kx = 0; kx < 3; ++kx) {
                            a += sw2[c * 9 + ky * 3 + kx] * sh[c][oy + ky][ox + kx];
                        }
                    }
                }
                acc[k] += fmaxf(a, 0.0f);
            }
            // No barrier needed: next decode writes ssp (disjoint from sh)
            // and its __syncthreads orders sh reuse.
        }
    }

    // ---- mean over T and store -------------------------------------------
    const float inv_t = 1.0f / (float)T_STEPS;
    #pragma unroll
    for (int k = 0; k < 4; ++k) {
        const int o  = tid + 256 * k;
        const int oy = o >> 5;
        const int ox = o & 31;
        out[(size_t)(y0 + oy) * IMG_W + (x0 + ox)] = acc[k] * inv_t;
    }
}

// ---------------------------------------------------------------------------
extern "C" void kernel_launch(void* const* d_in, const int* in_sizes, int n_in,
                              void* d_out, int out_size)
{
    const float* x_seq = (const float*)d_in[0];   // [96, 512, 512] fp32
    const float* w1    = (const float*)d_in[1];   // [4,1,3,3] fp32
    const float* w2    = (const float*)d_in[2];   // [1,4,3,3] fp32
    float*       out   = (float*)d_out;           // [512,512] fp32

    lif_spike_kernel<<<HW / 256, 128>>>(x_seq);   // 1024 blocks, 2 px/thread
    conv_accum_kernel<<<dim3(IMG_W / TILE, IMG_H / TILE), 256>>>(w1, w2, out);
}